// round 14
// baseline (speedup 1.0000x reference)
#include <cuda_runtime.h>
#include <cstdint>

#define Bq 4
#define Hh 16
#define Ss 2048
#define Dd 64
#define BM 128
#define BN 64
#define NKT 32
#define THREADS 512
#define PADK 68
#define PADV 72
#define SCALE2 0.18033688011112043f   // (1/8) * log2(e)
#define FULLM 0xffffffffu
#define N4 (Bq * Hh * Ss * Dd / 4)    // 2,097,152 float4 per tensor

__device__ float4 g_k4[N4];
__device__ float4 g_v4[N4];
__device__ unsigned g_maskbits[Bq * Ss * (Ss / 32)];

__device__ __forceinline__ float f2tff(float f) {
    unsigned u; asm("cvt.rna.tf32.f32 %0, %1;" : "=r"(u) : "f"(f)); return __uint_as_float(u);
}
__device__ __forceinline__ unsigned f2tfu(float f) {
    unsigned u; asm("cvt.rna.tf32.f32 %0, %1;" : "=r"(u) : "f"(f)); return u;
}
__device__ __forceinline__ float ex2f(float x) {
    float y; asm("ex2.approx.f32 %0, %1;" : "=f"(y) : "f"(x)); return y;
}
__device__ __forceinline__ uint32_t smem_u32(const void* p) {
    uint32_t a;
    asm("{ .reg .u64 t; cvta.to.shared.u64 t, %1; cvt.u32.u64 %0, t; }" : "=r"(a) : "l"(p));
    return a;
}
__device__ __forceinline__ void cpa16(uint32_t d, const float* s) {
    asm volatile("cp.async.cg.shared.global [%0], [%1], 16;" :: "r"(d), "l"(s));
}
__device__ __forceinline__ void cpacommit() { asm volatile("cp.async.commit_group;" ::: "memory"); }
template<int N> __device__ __forceinline__ void cpawait() {
    asm volatile("cp.async.wait_group %0;" :: "n"(N) : "memory");
}
__device__ __forceinline__ void mma_tf32(float c[4], const unsigned a[4], unsigned b0, unsigned b1) {
    asm volatile(
        "mma.sync.aligned.m16n8k8.row.col.f32.tf32.tf32.f32 "
        "{%0,%1,%2,%3},{%4,%5,%6,%7},{%8,%9},{%0,%1,%2,%3};\n"
        : "+f"(c[0]), "+f"(c[1]), "+f"(c[2]), "+f"(c[3])
        : "r"(a[0]), "r"(a[1]), "r"(a[2]), "r"(a[3]), "r"(b0), "r"(b1));
}

// ---------- prologue ----------
__global__ void pack_mask_kernel(const int* __restrict__ mask) {
    int gt = blockIdx.x * blockDim.x + threadIdx.x;
    unsigned w = __ballot_sync(FULLM, mask[gt] != 0);
    if ((threadIdx.x & 31) == 0) g_maskbits[gt >> 5] = w;
}
__global__ void preround_kernel(const float4* __restrict__ k, const float4* __restrict__ v) {
    int i = blockIdx.x * blockDim.x + threadIdx.x;
    float4 a = k[i];
    a.x = f2tff(a.x); a.y = f2tff(a.y); a.z = f2tff(a.z); a.w = f2tff(a.w);
    g_k4[i] = a;
    a = v[i];
    a.x = f2tff(a.x); a.y = f2tff(a.y); a.z = f2tff(a.z); a.w = f2tff(a.w);
    g_v4[i] = a;
}

__device__ __forceinline__ void stage64(uint32_t dst, const float* base, int kt, int tid, int pad) {
    #pragma unroll
    for (int i = 0; i < 2; i++) {
        int n = tid + i * THREADS;
        int row = n >> 4, c4 = n & 15;
        cpa16(dst + (unsigned)(row * pad + c4 * 4) * 4u,
              base + (size_t)(kt * BN + row) * Dd + c4 * 4);
    }
}

// smem float offsets: QS 128x68 (staging + O exchange), K 2x4352, V 2x4608, RS 256
#define KS_OFF 8704
#define VS_OFF (KS_OFF + 2 * 4352)    // 17408
#define RS_OFF (VS_OFF + 2 * 4608)    // 26624
#define SM_FLOATS (RS_OFF + 256)      // 26880 floats = 107520 B

__global__ __launch_bounds__(THREADS, 1)
void attn_kernel(const float* __restrict__ Qg, float* __restrict__ Og, float* __restrict__ Pg) {
    extern __shared__ float sm[];
    const uint32_t sb = smem_u32(sm);
    const int tid = threadIdx.x, lane = tid & 31, warp = tid >> 5;
    const int g = lane >> 2, qd = lane & 3, wm = warp >> 1, wn = warp & 1, r0 = wm * 16;

    const int hh = blockIdx.x, qt = blockIdx.y, bb = blockIdx.z;
    const size_t bh = (size_t)(bb * Hh + hh);
    const float* qptr  = Qg + (bh * Ss + (size_t)qt * BM) * Dd;
    const float* kbase = (const float*)g_k4 + bh * Ss * Dd;
    const float* vbase = (const float*)g_v4 + bh * Ss * Dd;
    float* score = Pg + bh * (size_t)Ss * Ss + (size_t)(qt * BM) * Ss;
    float* Og_t  = Og + (bh * Ss + (size_t)qt * BM) * Dd;
    const unsigned* mbase = g_maskbits + ((size_t)bb * Ss + (size_t)qt * BM) * (Ss / 32);

    // ---- stage Q raw (128x64 = 2048 float4), lift fragments, round once ----
    #pragma unroll
    for (int it = 0; it < 4; it++) {
        int n = tid + it * THREADS;
        int row = n >> 4, c4 = n & 15;
        cpa16(sb + (unsigned)(row * PADK + c4 * 4) * 4u, qptr + (size_t)row * Dd + c4 * 4);
    }
    cpacommit(); cpawait<0>();
    __syncthreads();

    unsigned qf[8][4];
    #pragma unroll
    for (int ks = 0; ks < 8; ks++) {
        const float* qr = sm + (r0 + g) * PADK + qd + 8 * ks;
        qf[ks][0] = f2tfu(qr[0]);
        qf[ks][1] = f2tfu(qr[8 * PADK]);
        qf[ks][2] = f2tfu(qr[4]);
        qf[ks][3] = f2tfu(qr[8 * PADK + 4]);
    }
    __syncthreads();

    const unsigned* mrow0 = mbase + (size_t)(r0 + g) * 64;
    const unsigned* mrow1 = mbase + (size_t)(r0 + g + 8) * 64;

    // ================= Phase A: row sums of exp =================
    float lacc[2] = {0.f, 0.f};

    stage64(sb + (unsigned)KS_OFF * 4u, kbase, 0, tid, PADK); cpacommit();

    for (int kt = 0; kt < NKT; kt++) {
        if (kt + 1 < NKT) {
            stage64(sb + (unsigned)(KS_OFF + ((kt + 1) & 1) * 4352) * 4u, kbase, kt + 1, tid, PADK);
            cpacommit();
            cpawait<1>();
        } else {
            cpawait<0>();
        }
        __syncthreads();
        const float* Kb = sm + KS_OFF + (kt & 1) * 4352;

        float sacc[4][4];
        #pragma unroll
        for (int j = 0; j < 4; j++)
            #pragma unroll
            for (int c = 0; c < 4; c++) sacc[j][c] = 0.f;

        #pragma unroll
        for (int ks = 0; ks < 8; ks++)
            #pragma unroll
            for (int j = 0; j < 4; j++) {
                const float* kr = Kb + (wn * 32 + 8 * j + g) * PADK + qd + 8 * ks;
                mma_tf32(sacc[j], qf[ks], __float_as_uint(kr[0]), __float_as_uint(kr[4]));
            }

        unsigned mw0 = mrow0[kt * 2 + wn];
        unsigned mw1 = mrow1[kt * 2 + wn];
        #pragma unroll
        for (int j = 0; j < 4; j++) {
            int b = 8 * j + 2 * qd;
            lacc[0] += ex2f(((mw0 >> b) & 1u)       ? sacc[j][0] * SCALE2 : 0.f);
            lacc[0] += ex2f(((mw0 >> (b + 1)) & 1u) ? sacc[j][1] * SCALE2 : 0.f);
            lacc[1] += ex2f(((mw1 >> b) & 1u)       ? sacc[j][2] * SCALE2 : 0.f);
            lacc[1] += ex2f(((mw1 >> (b + 1)) & 1u) ? sacc[j][3] * SCALE2 : 0.f);
        }
        __syncthreads();
    }

    // reduce l across qd group, then across wn halves via smem
    #pragma unroll
    for (int r = 0; r < 2; r++) {
        float v = lacc[r];
        v += __shfl_xor_sync(FULLM, v, 1);
        v += __shfl_xor_sync(FULLM, v, 2);
        if (qd == 0) sm[RS_OFF + (r0 + g + 8 * r) * 2 + wn] = v;
    }
    __syncthreads();
    float linv[2];
    #pragma unroll
    for (int r = 0; r < 2; r++) {
        int row = r0 + g + 8 * r;
        linv[r] = 1.0f / (sm[RS_OFF + row * 2] + sm[RS_OFF + row * 2 + 1]);
    }
    __syncthreads();

    // ================= Phase B: recompute, write p, split-key PV =================
    float oacc[8][4];
    #pragma unroll
    for (int jn = 0; jn < 8; jn++)
        #pragma unroll
        for (int c = 0; c < 4; c++) oacc[jn][c] = 0.f;

    stage64(sb + (unsigned)KS_OFF * 4u, kbase, 0, tid, PADK);
    stage64(sb + (unsigned)VS_OFF * 4u, vbase, 0, tid, PADV); cpacommit();

    const int srcA = (lane & ~3) | (qd >> 1);
    const int srcB = srcA + 2;

    for (int kt = 0; kt < NKT; kt++) {
        if (kt + 1 < NKT) {
            stage64(sb + (unsigned)(KS_OFF + ((kt + 1) & 1) * 4352) * 4u, kbase, kt + 1, tid, PADK);
            stage64(sb + (unsigned)(VS_OFF + ((kt + 1) & 1) * 4608) * 4u, vbase, kt + 1, tid, PADV);
            cpacommit();
            cpawait<1>();
        } else {
            cpawait<0>();
        }
        __syncthreads();
        const float* Kb = sm + KS_OFF + (kt & 1) * 4352;
        const float* Vb = sm + VS_OFF + (kt & 1) * 4608;

        float sacc[4][4];
        #pragma unroll
        for (int j = 0; j < 4; j++)
            #pragma unroll
            for (int c = 0; c < 4; c++) sacc[j][c] = 0.f;

        #pragma unroll
        for (int ks = 0; ks < 8; ks++)
            #pragma unroll
            for (int j = 0; j < 4; j++) {
                const float* kr = Kb + (wn * 32 + 8 * j + g) * PADK + qd + 8 * ks;
                mma_tf32(sacc[j], qf[ks], __float_as_uint(kr[0]), __float_as_uint(kr[4]));
            }

        // p (normalized): stream to gmem, round in place for PV
        unsigned mw0 = mrow0[kt * 2 + wn];
        unsigned mw1 = mrow1[kt * 2 + wn];
        #pragma unroll
        for (int j = 0; j < 4; j++) {
            int b = 8 * j + 2 * qd;
            float p0 = ex2f(((mw0 >> b) & 1u)       ? sacc[j][0] * SCALE2 : 0.f) * linv[0];
            float p1 = ex2f(((mw0 >> (b + 1)) & 1u) ? sacc[j][1] * SCALE2 : 0.f) * linv[0];
            float p2 = ex2f(((mw1 >> b) & 1u)       ? sacc[j][2] * SCALE2 : 0.f) * linv[1];
            float p3 = ex2f(((mw1 >> (b + 1)) & 1u) ? sacc[j][3] * SCALE2 : 0.f) * linv[1];
            int gcol = kt * 64 + wn * 32 + b;
            __stcs((float2*)(score + (size_t)(r0 + g) * Ss + gcol), make_float2(p0, p1));
            __stcs((float2*)(score + (size_t)(r0 + g + 8) * Ss + gcol), make_float2(p2, p3));
            sacc[j][0] = f2tff(p0); sacc[j][1] = f2tff(p1);
            sacc[j][2] = f2tff(p2); sacc[j][3] = f2tff(p3);
        }

        // split-key PV: C-frag -> A-frag via shuffles
        #pragma unroll
        for (int kk = 0; kk < 4; kk++) {
            float c0 = sacc[kk][0], c1 = sacc[kk][1], c2 = sacc[kk][2], c3 = sacc[kk][3];
            float s0a = __shfl_sync(FULLM, c0, srcA), s1a = __shfl_sync(FULLM, c1, srcA);
            float s2a = __shfl_sync(FULLM, c2, srcA), s3a = __shfl_sync(FULLM, c3, srcA);
            float s0b = __shfl_sync(FULLM, c0, srcB), s1b = __shfl_sync(FULLM, c1, srcB);
            float s2b = __shfl_sync(FULLM, c2, srcB), s3b = __shfl_sync(FULLM, c3, srcB);
            unsigned a[4];
            a[0] = __float_as_uint((qd & 1) ? s1a : s0a);
            a[1] = __float_as_uint((qd & 1) ? s3a : s2a);
            a[2] = __float_as_uint((qd & 1) ? s1b : s0b);
            a[3] = __float_as_uint((qd & 1) ? s3b : s2b);
            #pragma unroll
            for (int jn = 0; jn < 8; jn++) {
                const float* vr = Vb + (wn * 32 + 8 * kk + qd) * PADV + 8 * jn + g;
                mma_tf32(oacc[jn], a, __float_as_uint(vr[0]), __float_as_uint(vr[4 * PADV]));
            }
        }
        __syncthreads();
    }

    // ---- epilogue: combine the two key-half partial O's (reuse Q smem) ----
    if (wn == 1) {
        #pragma unroll
        for (int jn = 0; jn < 8; jn++) {
            int row = r0 + g, col = 8 * jn + 2 * qd;
            *(float2*)(sm + row * PADK + col) = make_float2(oacc[jn][0], oacc[jn][1]);
            *(float2*)(sm + (row + 8) * PADK + col) = make_float2(oacc[jn][2], oacc[jn][3]);
        }
    }
    __syncthreads();
    if (wn == 0) {
        #pragma unroll
        for (int jn = 0; jn < 8; jn++) {
            int row = r0 + g, col = 8 * jn + 2 * qd;
            float o0 = oacc[jn][0] + sm[row * PADK + col];
            float o1 = oacc[jn][1] + sm[row * PADK + col + 1];
            float o2 = oacc[jn][2] + sm[(row + 8) * PADK + col];
            float o3 = oacc[jn][3] + sm[(row + 8) * PADK + col + 1];
            *(float2*)(Og_t + (size_t)row * Dd + col) = make_float2(o0, o1);
            *(float2*)(Og_t + (size_t)(row + 8) * Dd + col) = make_float2(o2, o3);
        }
    }
}

extern "C" void kernel_launch(void* const* d_in, const int* in_sizes, int n_in,
                              void* d_out, int out_size) {
    const float* q = (const float*)d_in[0];
    const float* k = (const float*)d_in[1];
    const float* v = (const float*)d_in[2];
    const int* mask = (const int*)d_in[3];

    float* out = (float*)d_out;
    float* score = out + (size_t)Bq * Hh * Ss * Dd;   // output first, then score

    preround_kernel<<<N4 / 256, 256>>>((const float4*)k, (const float4*)v);
    pack_mask_kernel<<<(Bq * Ss * Ss) / 256, 256>>>(mask);

    size_t smem = (size_t)SM_FLOATS * sizeof(float);  // 107,520 B
    cudaFuncSetAttribute(attn_kernel, cudaFuncAttributeMaxDynamicSharedMemorySize, (int)smem);
    dim3 grid(Hh, Ss / BM, Bq);
    attn_kernel<<<grid, THREADS, smem>>>(q, out, score);
}

// round 17
// speedup vs baseline: 1.1371x; 1.1371x over previous
#include <cuda_runtime.h>
#include <cstdint>

#define Bq 4
#define Hh 16
#define Ss 2048
#define Dd 64
#define BM 128
#define BN 64
#define NKT 32
#define THREADS 256
#define PAD 72
#define KBUF (64 * PAD)               // 4608 floats per K/V tile buffer
#define SCALE2 0.18033688011112043f   // (1/8) * log2(e)
#define FULLM 0xffffffffu
#define NE (Bq * Hh * Ss * Dd)        // 8,388,608 floats per tensor

__device__ float g_kp[NE];            // K, d-pairs interleaved within 8-groups
__device__ float g_vt[NE];            // V transposed [bh][d][s], s pair-permuted
__device__ float g_linv[Bq * Hh * Ss];
__device__ unsigned g_maskbits[Bq * Ss * (Ss / 32)];

__device__ __forceinline__ float f2tff(float f) {
    unsigned u; asm("cvt.rna.tf32.f32 %0, %1;" : "=r"(u) : "f"(f)); return __uint_as_float(u);
}
__device__ __forceinline__ unsigned f2tfu(float f) {
    unsigned u; asm("cvt.rna.tf32.f32 %0, %1;" : "=r"(u) : "f"(f)); return u;
}
__device__ __forceinline__ float ex2f(float x) {
    float y; asm("ex2.approx.f32 %0, %1;" : "=f"(y) : "f"(x)); return y;
}
__device__ __forceinline__ uint32_t smem_u32(const void* p) {
    uint32_t a;
    asm("{ .reg .u64 t; cvta.to.shared.u64 t, %1; cvt.u32.u64 %0, t; }" : "=r"(a) : "l"(p));
    return a;
}
__device__ __forceinline__ void cpa16(uint32_t d, const float* s) {
    asm volatile("cp.async.cg.shared.global [%0], [%1], 16;" :: "r"(d), "l"(s));
}
__device__ __forceinline__ void cpacommit() { asm volatile("cp.async.commit_group;" ::: "memory"); }
template<int N> __device__ __forceinline__ void cpawait() {
    asm volatile("cp.async.wait_group %0;" :: "n"(N) : "memory");
}
__device__ __forceinline__ void mma_tf32(float c[4], const unsigned a[4], unsigned b0, unsigned b1) {
    asm volatile(
        "mma.sync.aligned.m16n8k8.row.col.f32.tf32.tf32.f32 "
        "{%0,%1,%2,%3},{%4,%5,%6,%7},{%8,%9},{%0,%1,%2,%3};\n"
        : "+f"(c[0]), "+f"(c[1]), "+f"(c[2]), "+f"(c[3])
        : "r"(a[0]), "r"(a[1]), "r"(a[2]), "r"(a[3]), "r"(b0), "r"(b1));
}

// ---------------- prologue ----------------
__global__ void pack_mask_kernel(const int* __restrict__ mask) {
    int gt = blockIdx.x * blockDim.x + threadIdx.x;
    unsigned w = __ballot_sync(FULLM, mask[gt] != 0);
    if ((threadIdx.x & 31) == 0) g_maskbits[gt >> 5] = w;
}

// K: per 8-col group, interleave pairs (w -> (w&3)*2 + (w>>2)); round to tf32
__global__ void permk_kernel(const float* __restrict__ k) {
    int i = blockIdx.x * blockDim.x + threadIdx.x;      // one thread per 8-col group
    const float4* src = (const float4*)(k + (size_t)i * 8);
    float4 lo = src[0], hi = src[1];
    float4 o0 = make_float4(f2tff(lo.x), f2tff(hi.x), f2tff(lo.y), f2tff(hi.y));
    float4 o1 = make_float4(f2tff(lo.z), f2tff(hi.z), f2tff(lo.w), f2tff(hi.w));
    float4* dst = (float4*)(g_kp + (size_t)i * 8);
    dst[0] = o0; dst[1] = o1;
}

// V: transpose [s][d] -> [d][s] per bh, s pair-permuted within 8-groups; tf32 round
__global__ void transv_kernel(const float* __restrict__ v) {
    __shared__ float ts[64][65];
    const int bh = blockIdx.y, sblk = blockIdx.x;       // 64 x 32
    const int tid = threadIdx.x;
    const float* src = v + ((size_t)bh * Ss + (size_t)sblk * 64) * Dd;
    #pragma unroll
    for (int it = 0; it < 4; it++) {
        int n = tid + it * 256;                          // 1024 float4
        int r = n >> 4, c4 = n & 15;
        float4 val = *(const float4*)(src + (size_t)r * Dd + c4 * 4);
        ts[r][c4 * 4]     = val.x;
        ts[r][c4 * 4 + 1] = val.y;
        ts[r][c4 * 4 + 2] = val.z;
        ts[r][c4 * 4 + 3] = val.w;
    }
    __syncthreads();
    #pragma unroll
    for (int it = 0; it < 2; it++) {
        int task = tid + it * 256;                       // 512 tasks: (d, s-group)
        int d = task >> 3, grp = task & 7;
        int s0 = grp * 8;
        float w0 = ts[s0][d],     w1 = ts[s0 + 1][d], w2 = ts[s0 + 2][d], w3 = ts[s0 + 3][d];
        float w4 = ts[s0 + 4][d], w5 = ts[s0 + 5][d], w6 = ts[s0 + 6][d], w7 = ts[s0 + 7][d];
        float4 o0 = make_float4(f2tff(w0), f2tff(w4), f2tff(w1), f2tff(w5));
        float4 o1 = make_float4(f2tff(w2), f2tff(w6), f2tff(w3), f2tff(w7));
        float4* dst = (float4*)(g_vt + ((size_t)bh * Dd + d) * Ss + (size_t)sblk * 64 + s0);
        dst[0] = o0; dst[1] = o1;
    }
}

// stage one 64-row x 64-col tile (any source with row stride `rstride`)
__device__ __forceinline__ void stage64(uint32_t dst, const float* base, size_t rstride,
                                        int col0, int tid) {
    #pragma unroll
    for (int i = 0; i < 4; i++) {
        int n = tid + i * THREADS;
        int row = n >> 4, c4 = n & 15;
        cpa16(dst + (unsigned)(row * PAD + c4 * 4) * 4u,
              base + (size_t)row * rstride + col0 + c4 * 4);
    }
}

// ================= Kernel A: row sums -> g_linv =================
// smem: Q staging 128x72 = 9216 overlaps K bufs 3x4608 = 13824; RS 256
#define A_RS 13824
#define A_FLOATS (A_RS + 256)

__global__ __launch_bounds__(THREADS, 2)
void sums_kernel(const float* __restrict__ Qg) {
    extern __shared__ float sm[];
    const uint32_t sb = smem_u32(sm);
    const int tid = threadIdx.x, lane = tid & 31, warp = tid >> 5;
    const int g = lane >> 2, qd = lane & 3, wm = warp >> 1, wn = warp & 1, r0 = wm * 32;

    const int hh = blockIdx.x, qt = blockIdx.y, bb = blockIdx.z;
    const size_t bh = (size_t)(bb * Hh + hh);
    const float* qptr  = Qg + (bh * Ss + (size_t)qt * BM) * Dd;
    const float* kbase = g_kp + bh * Ss * Dd;              // [s][d'] rows of 64
    const unsigned* mbase = g_maskbits + ((size_t)bb * Ss + (size_t)qt * BM) * (Ss / 32);

    // stage Q raw, lift fragments (round once here)
    #pragma unroll
    for (int it = 0; it < 8; it++) {
        int n = tid + it * THREADS;
        int row = n >> 4, c4 = n & 15;
        cpa16(sb + (unsigned)(row * PAD + c4 * 4) * 4u, qptr + (size_t)row * Dd + c4 * 4);
    }
    cpacommit(); cpawait<0>();
    __syncthreads();

    unsigned qf[2][8][4];
    #pragma unroll
    for (int i = 0; i < 2; i++)
        #pragma unroll
        for (int ks = 0; ks < 8; ks++) {
            const float* qr = sm + (r0 + 16 * i + g) * PAD + qd + 8 * ks;
            qf[i][ks][0] = f2tfu(qr[0]);
            qf[i][ks][1] = f2tfu(qr[8 * PAD]);
            qf[i][ks][2] = f2tfu(qr[4]);
            qf[i][ks][3] = f2tfu(qr[8 * PAD + 4]);
        }
    __syncthreads();

    float lacc[2][2] = {{0.f, 0.f}, {0.f, 0.f}};

    stage64(sb, kbase, Dd, 0, tid); cpacommit();
    stage64(sb + (unsigned)KBUF * 4u, kbase + (size_t)BN * Dd, Dd, 0, tid); cpacommit();

    for (int kt = 0; kt < NKT; kt++) {
        if (kt == NKT - 1) cpawait<0>(); else cpawait<1>();
        __syncthreads();
        if (kt + 2 < NKT) {
            stage64(sb + (unsigned)(((kt + 2) % 3) * KBUF) * 4u,
                    kbase + (size_t)(kt + 2) * BN * Dd, Dd, 0, tid);
            cpacommit();
        }
        const float* Kb = sm + (kt % 3) * KBUF;

        float sacc[2][4][4];
        #pragma unroll
        for (int i = 0; i < 2; i++)
            #pragma unroll
            for (int j = 0; j < 4; j++)
                #pragma unroll
                for (int c = 0; c < 4; c++) sacc[i][j][c] = 0.f;

        #pragma unroll
        for (int ks = 0; ks < 8; ks++)
            #pragma unroll
            for (int j = 0; j < 4; j++) {
                float2 b = *(const float2*)(Kb + (wn * 32 + 8 * j + g) * PAD + 8 * ks + 2 * qd);
                unsigned b0 = __float_as_uint(b.x), b1 = __float_as_uint(b.y);
                mma_tf32(sacc[0][j], qf[0][ks], b0, b1);
                mma_tf32(sacc[1][j], qf[1][ks], b0, b1);
            }

        #pragma unroll
        for (int i = 0; i < 2; i++) {
            unsigned mw0 = mbase[(size_t)(r0 + 16 * i + g) * 64 + kt * 2 + wn];
            unsigned mw1 = mbase[(size_t)(r0 + 16 * i + g + 8) * 64 + kt * 2 + wn];
            #pragma unroll
            for (int j = 0; j < 4; j++) {
                int b = 8 * j + 2 * qd;
                lacc[i][0] += ex2f(((mw0 >> b) & 1u)       ? sacc[i][j][0] * SCALE2 : 0.f);
                lacc[i][0] += ex2f(((mw0 >> (b + 1)) & 1u) ? sacc[i][j][1] * SCALE2 : 0.f);
                lacc[i][1] += ex2f(((mw1 >> b) & 1u)       ? sacc[i][j][2] * SCALE2 : 0.f);
                lacc[i][1] += ex2f(((mw1 >> (b + 1)) & 1u) ? sacc[i][j][3] * SCALE2 : 0.f);
            }
        }
    }

    #pragma unroll
    for (int i = 0; i < 2; i++)
        #pragma unroll
        for (int r = 0; r < 2; r++) {
            float v = lacc[i][r];
            v += __shfl_xor_sync(FULLM, v, 1);
            v += __shfl_xor_sync(FULLM, v, 2);
            if (qd == 0) sm[A_RS + (r0 + 16 * i + g + 8 * r) * 2 + wn] = v;
        }
    __syncthreads();
    if (tid < BM) {
        float l = sm[A_RS + tid * 2] + sm[A_RS + tid * 2 + 1];
        g_linv[bh * Ss + (size_t)qt * BM + tid] = 1.0f / l;
    }
}

// ================= Kernel B: recompute, write p, split-key PV =================
// smem: QS 128x72 = 9216 (staging + O exchange), K 3x4608, V 3x4608 -> 36864 fl
#define B_KS 9216
#define B_VS (B_KS + 3 * KBUF)
#define B_FLOATS (B_VS + 3 * KBUF)

__global__ __launch_bounds__(THREADS, 1)
void attn_kernel(const float* __restrict__ Qg, float* __restrict__ Og, float* __restrict__ Pg) {
    extern __shared__ float sm[];
    const uint32_t sb = smem_u32(sm);
    const int tid = threadIdx.x, lane = tid & 31, warp = tid >> 5;
    const int g = lane >> 2, qd = lane & 3, wm = warp >> 1, wn = warp & 1, r0 = wm * 32;

    const int hh = blockIdx.x, qt = blockIdx.y, bb = blockIdx.z;
    const size_t bh = (size_t)(bb * Hh + hh);
    const float* qptr  = Qg + (bh * Ss + (size_t)qt * BM) * Dd;
    const float* kbase = g_kp + bh * Ss * Dd;              // [s][d']
    const float* vbase = g_vt + bh * Ss * Dd;              // [d][s'], row stride Ss
    float* score = Pg + bh * (size_t)Ss * Ss + (size_t)(qt * BM) * Ss;
    float* Og_t  = Og + (bh * Ss + (size_t)qt * BM) * Dd;
    const unsigned* mbase = g_maskbits + ((size_t)bb * Ss + (size_t)qt * BM) * (Ss / 32);

    // stage Q raw, lift fragments
    #pragma unroll
    for (int it = 0; it < 8; it++) {
        int n = tid + it * THREADS;
        int row = n >> 4, c4 = n & 15;
        cpa16(sb + (unsigned)(row * PAD + c4 * 4) * 4u, qptr + (size_t)row * Dd + c4 * 4);
    }
    cpacommit(); cpawait<0>();
    __syncthreads();

    unsigned qf[2][8][4];
    #pragma unroll
    for (int i = 0; i < 2; i++)
        #pragma unroll
        for (int ks = 0; ks < 8; ks++) {
            const float* qr = sm + (r0 + 16 * i + g) * PAD + qd + 8 * ks;
            qf[i][ks][0] = f2tfu(qr[0]);
            qf[i][ks][1] = f2tfu(qr[8 * PAD]);
            qf[i][ks][2] = f2tfu(qr[4]);
            qf[i][ks][3] = f2tfu(qr[8 * PAD + 4]);
        }

    float linv[2][2];
    #pragma unroll
    for (int i = 0; i < 2; i++)
        #pragma unroll
        for (int r = 0; r < 2; r++)
            linv[i][r] = g_linv[bh * Ss + (size_t)qt * BM + r0 + 16 * i + g + 8 * r];

    float oacc[2][8][4];
    #pragma unroll
    for (int i = 0; i < 2; i++)
        #pragma unroll
        for (int jn = 0; jn < 8; jn++)
            #pragma unroll
            for (int c = 0; c < 4; c++) oacc[i][jn][c] = 0.f;

    stage64(sb + (unsigned)B_KS * 4u, kbase, Dd, 0, tid);
    stage64(sb + (unsigned)B_VS * 4u, vbase, Ss, 0, tid); cpacommit();
    stage64(sb + (unsigned)(B_KS + KBUF) * 4u, kbase + (size_t)BN * Dd, Dd, 0, tid);
    stage64(sb + (unsigned)(B_VS + KBUF) * 4u, vbase, Ss, BN, tid); cpacommit();

    const int srcA = (lane & ~3) | (qd >> 1);
    const int srcB = srcA + 2;

    for (int kt = 0; kt < NKT; kt++) {
        if (kt == NKT - 1) cpawait<0>(); else cpawait<1>();
        __syncthreads();
        if (kt + 2 < NKT) {
            stage64(sb + (unsigned)(B_KS + ((kt + 2) % 3) * KBUF) * 4u,
                    kbase + (size_t)(kt + 2) * BN * Dd, Dd, 0, tid);
            stage64(sb + (unsigned)(B_VS + ((kt + 2) % 3) * KBUF) * 4u,
                    vbase, Ss, (kt + 2) * BN, tid);
            cpacommit();
        }
        const float* Kb = sm + B_KS + (kt % 3) * KBUF;
        const float* Vb = sm + B_VS + (kt % 3) * KBUF;

        float sacc[2][4][4];
        #pragma unroll
        for (int i = 0; i < 2; i++)
            #pragma unroll
            for (int j = 0; j < 4; j++)
                #pragma unroll
                for (int c = 0; c < 4; c++) sacc[i][j][c] = 0.f;

        #pragma unroll
        for (int ks = 0; ks < 8; ks++)
            #pragma unroll
            for (int j = 0; j < 4; j++) {
                float2 b = *(const float2*)(Kb + (wn * 32 + 8 * j + g) * PAD + 8 * ks + 2 * qd);
                unsigned b0 = __float_as_uint(b.x), b1 = __float_as_uint(b.y);
                mma_tf32(sacc[0][j], qf[0][ks], b0, b1);
                mma_tf32(sacc[1][j], qf[1][ks], b0, b1);
            }

        // p (normalized): stream to gmem, round in place for PV
        #pragma unroll
        for (int i = 0; i < 2; i++) {
            unsigned mw0 = mbase[(size_t)(r0 + 16 * i + g) * 64 + kt * 2 + wn];
            unsigned mw1 = mbase[(size_t)(r0 + 16 * i + g + 8) * 64 + kt * 2 + wn];
            #pragma unroll
            for (int j = 0; j < 4; j++) {
                int b = 8 * j + 2 * qd;
                float p0 = ex2f(((mw0 >> b) & 1u)       ? sacc[i][j][0] * SCALE2 : 0.f) * linv[i][0];
                float p1 = ex2f(((mw0 >> (b + 1)) & 1u) ? sacc[i][j][1] * SCALE2 : 0.f) * linv[i][0];
                float p2 = ex2f(((mw1 >> b) & 1u)       ? sacc[i][j][2] * SCALE2 : 0.f) * linv[i][1];
                float p3 = ex2f(((mw1 >> (b + 1)) & 1u) ? sacc[i][j][3] * SCALE2 : 0.f) * linv[i][1];
                int gcol = kt * 64 + wn * 32 + b;
                __stcs((float2*)(score + (size_t)(r0 + 16 * i + g) * Ss + gcol), make_float2(p0, p1));
                __stcs((float2*)(score + (size_t)(r0 + 16 * i + g + 8) * Ss + gcol), make_float2(p2, p3));
                sacc[i][j][0] = f2tff(p0); sacc[i][j][1] = f2tff(p1);
                sacc[i][j][2] = f2tff(p2); sacc[i][j][3] = f2tff(p3);
            }
        }

        // split-key PV: C-frag -> A-frag via shuffles; V b-frags from [d][s'] tile
        #pragma unroll
        for (int kk = 0; kk < 4; kk++) {
            unsigned a[2][4];
            #pragma unroll
            for (int i = 0; i < 2; i++) {
                float c0 = sacc[i][kk][0], c1 = sacc[i][kk][1];
                float c2 = sacc[i][kk][2], c3 = sacc[i][kk][3];
                float s0a = __shfl_sync(FULLM, c0, srcA), s1a = __shfl_sync(FULLM, c1, srcA);
                float s2a = __shfl_sync(FULLM, c2, srcA), s3a = __shfl_sync(FULLM, c3, srcA);
                float s0b = __shfl_sync(FULLM, c0, srcB), s1b = __shfl_sync(FULLM, c1, srcB);
                float s2b = __shfl_sync(FULLM, c2, srcB), s3b = __shfl_sync(FULLM, c3, srcB);
                a[i][0] = __float_as_uint((qd & 1) ? s1a : s0a);
                a[i][1] = __float_as_uint((qd & 1) ? s3a : s2a);
                a[i][2] = __float_as_uint((qd & 1) ? s1b : s0b);
                a[i][3] = __float_as_uint((qd & 1) ? s3b : s2b);
            }
            #pragma unroll
            for (int jn = 0; jn < 8; jn++) {
                float2 b = *(const float2*)(Vb + (8 * jn + g) * PAD + wn * 32 + 8 * kk + 2 * qd);
                unsigned b0 = __float_as_uint(b.x), b1 = __float_as_uint(b.y);
                mma_tf32(oacc[0][jn], a[0], b0, b1);
                mma_tf32(oacc[1][jn], a[1], b0, b1);
            }
        }
    }

    // epilogue: combine the two key-half partial O's (reuse QS region)
    __syncthreads();
    if (wn == 1) {
        #pragma unroll
        for (int i = 0; i < 2; i++)
            #pragma unroll
            for (int jn = 0; jn < 8; jn++) {
                int row = r0 + 16 * i + g, col = 8 * jn + 2 * qd;
                *(float2*)(sm + row * PAD + col) = make_float2(oacc[i][jn][0], oacc[i][jn][1]);
                *(float2*)(sm + (row + 8) * PAD + col) = make_float2(oacc[i][jn][2], oacc[i][jn][3]);
            }
    }
    __syncthreads();
    if (wn == 0) {
        #pragma unroll
        for (int i = 0; i < 2; i++)
            #pragma unroll
            for (int jn = 0; jn < 8; jn++) {
                int row = r0 + 16 * i + g, col = 8 * jn + 2 * qd;
                float o0 = oacc[i][jn][0] + sm[row * PAD + col];
                float o1 = oacc[i][jn][1] + sm[row * PAD + col + 1];
                float o2 = oacc[i][jn][2] + sm[(row + 8) * PAD + col];
                float o3 = oacc[i][jn][3] + sm[(row + 8) * PAD + col + 1];
                *(float2*)(Og_t + (size_t)row * Dd + col) = make_float2(o0, o1);
                *(float2*)(Og_t + (size_t)(row + 8) * Dd + col) = make_float2(o2, o3);
            }
    }
}

extern "C" void kernel_launch(void* const* d_in, const int* in_sizes, int n_in,
                              void* d_out, int out_size) {
    const float* q = (const float*)d_in[0];
    const float* k = (const float*)d_in[1];
    const float* v = (const float*)d_in[2];
    const int* mask = (const int*)d_in[3];

    float* out = (float*)d_out;
    float* score = out + (size_t)Bq * Hh * Ss * Dd;   // output first, then score

    permk_kernel<<<NE / 8 / 256, 256>>>(k);
    {
        dim3 tg(32, Bq * Hh);
        transv_kernel<<<tg, 256>>>(v);
    }
    pack_mask_kernel<<<(Bq * Ss * Ss) / 256, 256>>>(mask);

    dim3 grid(Hh, Ss / BM, Bq);
    size_t smemA = (size_t)A_FLOATS * sizeof(float);   // 56,320 B -> 2 CTAs/SM
    size_t smemB = (size_t)B_FLOATS * sizeof(float);   // 147,456 B -> 1 CTA/SM
    cudaFuncSetAttribute(sums_kernel, cudaFuncAttributeMaxDynamicSharedMemorySize, (int)smemA);
    cudaFuncSetAttribute(attn_kernel, cudaFuncAttributeMaxDynamicSharedMemorySize, (int)smemB);

    sums_kernel<<<grid, THREADS, smemA>>>(q);
    attn_kernel<<<grid, THREADS, smemB>>>(q, out, score);
}